// round 12
// baseline (speedup 1.0000x reference)
#include <cuda_runtime.h>
#include <cuda_fp16.h>
#include <cuda_bf16.h>
#include <math.h>

#define N_ATOMS 1000000
#define N_PAD   1000064        // next multiple of 128
#define N_EDGES 4000000
#define NGRAPH  1024
#define IN_F    64
#define HF      32
#define LN_EPS  1e-5f
#define TILE_I  128
#define TILE_N  128
#define XS_STR  68
#define MS_STR  36
#define DSPLIT  500000         // dst-range split point for L2-blocked scatter

// -------- scratch (device globals: zero-initialized at module load) --------
__device__ float  g_deg_out[N_ATOMS];   // invariant: all-zero between launches
__device__ float  g_deg_in[N_ATOMS];    // invariant: all-zero between launches
__device__ float  g_ns[N_PAD];          // pad entries stay 0
__device__ float  g_nd[N_PAD];          // pad entries stay 0
__device__ __half g_hs[N_PAD * HF];     // fp16 messages (pad rows zeroed, never gathered)
__device__ __half g_m [N_PAD * HF];     // fp16 scatter accumulator (all-zero invariant)

// -------- helpers --------
__device__ __forceinline__ float elu1(float x) { return x > 0.f ? x : __expf(x) - 1.f; }
__device__ __forceinline__ float sum8(float v) {
    v += __shfl_xor_sync(0xffffffffu, v, 1);
    v += __shfl_xor_sync(0xffffffffu, v, 2);
    v += __shfl_xor_sync(0xffffffffu, v, 4);
    return v;
}

// -------- degree + norm --------
__global__ void degree_kernel(const int* __restrict__ src, const int* __restrict__ dst) {
    int e = blockIdx.x * blockDim.x + threadIdx.x;
    if (e < N_EDGES) {
        atomicAdd(&g_deg_out[src[e]], 1.f);
        atomicAdd(&g_deg_in [dst[e]], 1.f);
    }
}
// reads degrees, writes norms, restores zero invariant, zeroes output buffer
__global__ void norm_kernel(float* __restrict__ out) {
    int i = blockIdx.x * blockDim.x + threadIdx.x;
    if (i < NGRAPH) out[i] = 0.f;
    if (i < N_ATOMS) {
        float dout = g_deg_out[i], din = g_deg_in[i];
        g_ns[i] = dout > 0.f ? rsqrtf(dout) : 0.f;
        g_nd[i] = din  > 0.f ? rsqrtf(din)  : 0.f;
        g_deg_out[i] = 0.f;
        g_deg_in [i] = 0.f;
    }
}

__device__ __forceinline__ void store_h4(__half* p, float a, float b, float c, float d) {
    __half2 lo = __floats2half2_rn(a, b);
    __half2 hi = __floats2half2_rn(c, d);
    uint2 v;
    v.x = *reinterpret_cast<unsigned*>(&lo);
    v.y = *reinterpret_cast<unsigned*>(&hi);
    *reinterpret_cast<uint2*>(p) = v;
}

#define FMA16(acc, xv, wv0, wv1, wv2, wv3)                                                     \
    do {                                                                                       \
        acc.x = fmaf(xv.x, wv0.x, acc.x); acc.y = fmaf(xv.x, wv0.y, acc.y);                    \
        acc.z = fmaf(xv.x, wv0.z, acc.z); acc.w = fmaf(xv.x, wv0.w, acc.w);                    \
        acc.x = fmaf(xv.y, wv1.x, acc.x); acc.y = fmaf(xv.y, wv1.y, acc.y);                    \
        acc.z = fmaf(xv.y, wv1.z, acc.z); acc.w = fmaf(xv.y, wv1.w, acc.w);                    \
        acc.x = fmaf(xv.z, wv2.x, acc.x); acc.y = fmaf(xv.z, wv2.y, acc.y);                    \
        acc.z = fmaf(xv.z, wv2.z, acc.z); acc.w = fmaf(xv.z, wv2.w, acc.w);                    \
        acc.x = fmaf(xv.w, wv3.x, acc.x); acc.y = fmaf(xv.w, wv3.y, acc.y);                    \
        acc.z = fmaf(xv.w, wv3.z, acc.z); acc.w = fmaf(xv.w, wv3.w, acc.w);                    \
    } while (0)

// -------- input MLP (tiled, 4 nodes/thread) --------
__global__ __launch_bounds__(256) void input_mlp_tile(
        const float* __restrict__ feats,
        const float* __restrict__ w0,  const float* __restrict__ b0,
        const float* __restrict__ g0,  const float* __restrict__ be0) {
    __shared__ float xs[TILE_I * XS_STR];
    __shared__ float sw[IN_F * HF];
    int t = threadIdx.x;
    int base = blockIdx.x * TILE_I;

    for (int i = t; i < IN_F * HF / 4; i += 256)
        reinterpret_cast<float4*>(sw)[i] = reinterpret_cast<const float4*>(w0)[i];
    #pragma unroll
    for (int i = t; i < TILE_I * (IN_F / 4); i += 256) {
        int n = i >> 4, c = i & 15;
        float4 v = make_float4(0.f, 0.f, 0.f, 0.f);
        if (base + n < N_ATOMS)
            v = reinterpret_cast<const float4*>(feats)[(size_t)(base + n) * 16 + c];
        *reinterpret_cast<float4*>(&xs[n * XS_STR + c * 4]) = v;
    }
    __syncthreads();

    int oq = t & 7, nq = t >> 3;
    float4 bv = reinterpret_cast<const float4*>(b0)[oq];
    float4 acc[4];
    #pragma unroll
    for (int j = 0; j < 4; j++) acc[j] = bv;

    #pragma unroll
    for (int k = 0; k < IN_F; k += 4) {
        float4 wv0 = *reinterpret_cast<const float4*>(&sw[(k+0) * HF + oq * 4]);
        float4 wv1 = *reinterpret_cast<const float4*>(&sw[(k+1) * HF + oq * 4]);
        float4 wv2 = *reinterpret_cast<const float4*>(&sw[(k+2) * HF + oq * 4]);
        float4 wv3 = *reinterpret_cast<const float4*>(&sw[(k+3) * HF + oq * 4]);
        #pragma unroll
        for (int j = 0; j < 4; j++) {
            float4 xv = *reinterpret_cast<const float4*>(&xs[(nq + j * 32) * XS_STR + k]);
            FMA16(acc[j], xv, wv0, wv1, wv2, wv3);
        }
    }

    float4 gv  = reinterpret_cast<const float4*>(g0)[oq];
    float4 bev = reinterpret_cast<const float4*>(be0)[oq];
    #pragma unroll
    for (int j = 0; j < 4; j++) {
        int node = base + nq + j * 32;
        float4 a = acc[j];
        float mu = sum8(a.x + a.y + a.z + a.w) * (1.f / HF);
        float dx = a.x - mu, dy = a.y - mu, dz = a.z - mu, dw = a.w - mu;
        float var = sum8(dx*dx + dy*dy + dz*dz + dw*dw) * (1.f / HF);
        float r = rsqrtf(var + LN_EPS);
        if (node < N_ATOMS) {
            float s = g_ns[node];
            store_h4(&g_hs[(size_t)node * HF + oq * 4],
                     elu1(dx * r * gv.x + bev.x) * s,
                     elu1(dy * r * gv.y + bev.y) * s,
                     elu1(dz * r * gv.z + bev.z) * s,
                     elu1(dw * r * gv.w + bev.w) * s);
        }
    }
}

// -------- edge scatter (dst-range blocked): m[dst] += hs[src] for dst in [lo, hi) --------
__global__ void scatter_kernel(const int* __restrict__ src, const int* __restrict__ dst,
                               int lo, int hi) {
    long long idx = (long long)blockIdx.x * blockDim.x + threadIdx.x;
    if (idx >= (long long)N_EDGES * 4) return;
    int e = (int)(idx >> 2);
    int p = ((int)idx & 3) * 8;
    int d = __ldg(&dst[e]);
    if (d < lo || d >= hi) return;
    int s = __ldg(&src[e]);
    uint4 v = __ldg(reinterpret_cast<const uint4*>(&g_hs[(size_t)s * HF + p]));
    __half* mp = &g_m[(size_t)d * HF + p];
    asm volatile("red.global.add.noftz.v4.f16x2 [%0], {%1, %2, %3, %4};"
                 :: "l"(mp), "r"(v.x), "r"(v.y), "r"(v.z), "r"(v.w) : "memory");
}

// -------- conv epilogue + node MLP block (tiled, 4 nodes/thread, smem-lean) --------
// MODE 0: -> g_hs (half, *ns). MODE 1: fused head -> per-graph sums.
template<int MODE>
__global__ __launch_bounds__(256) void node_block_tile(
        const float* __restrict__ wc, const float* __restrict__ bc,
        const float* __restrict__ w,  const float* __restrict__ b,
        const float* __restrict__ g,  const float* __restrict__ be,
        const float* __restrict__ wout, const float* __restrict__ bout,
        const int* __restrict__ gid, float* __restrict__ out) {
    __shared__ float ms[TILE_N * MS_STR];              // reused for intermediate t
    __shared__ float swc[HF * HF];
    __shared__ float sw [HF * HF];
    __shared__ float sacc[MODE == 1 ? NGRAPH : 1];
    int t = threadIdx.x;
    int base = blockIdx.x * TILE_N;

    for (int i = t; i < HF * HF; i += 256) { swc[i] = wc[i]; sw[i] = w[i]; }
    if (MODE == 1)
        for (int i = t; i < NGRAPH; i += 256) sacc[i] = 0.f;
    #pragma unroll
    for (int i = t; i < TILE_N * 4; i += 256) {
        int n = i >> 2, c = i & 3;
        uint4* gp = reinterpret_cast<uint4*>(&g_m[(size_t)(base + n) * HF + c * 8]);
        uint4 v = *gp;
        float ndv = g_nd[base + n];
        float* mrow = &ms[n * MS_STR + c * 8];
        __half2 h;
        h = *reinterpret_cast<__half2*>(&v.x); float2 f0 = __half22float2(h);
        h = *reinterpret_cast<__half2*>(&v.y); float2 f1 = __half22float2(h);
        h = *reinterpret_cast<__half2*>(&v.z); float2 f2 = __half22float2(h);
        h = *reinterpret_cast<__half2*>(&v.w); float2 f3 = __half22float2(h);
        mrow[0] = f0.x * ndv; mrow[1] = f0.y * ndv;
        mrow[2] = f1.x * ndv; mrow[3] = f1.y * ndv;
        mrow[4] = f2.x * ndv; mrow[5] = f2.y * ndv;
        mrow[6] = f3.x * ndv; mrow[7] = f3.y * ndv;
        *gp = make_uint4(0u, 0u, 0u, 0u);
    }
    __syncthreads();

    int oq = t & 7, nq = t >> 3;

    // GEMM1 into registers: acc = ms @ wc + bc
    float4 acc[4];
    {
        float4 bv = reinterpret_cast<const float4*>(bc)[oq];
        #pragma unroll
        for (int j = 0; j < 4; j++) acc[j] = bv;
        #pragma unroll
        for (int k = 0; k < HF; k += 4) {
            float4 wv0 = *reinterpret_cast<const float4*>(&swc[(k+0) * HF + oq * 4]);
            float4 wv1 = *reinterpret_cast<const float4*>(&swc[(k+1) * HF + oq * 4]);
            float4 wv2 = *reinterpret_cast<const float4*>(&swc[(k+2) * HF + oq * 4]);
            float4 wv3 = *reinterpret_cast<const float4*>(&swc[(k+3) * HF + oq * 4]);
            #pragma unroll
            for (int j = 0; j < 4; j++) {
                float4 xv = *reinterpret_cast<const float4*>(&ms[(nq + j * 32) * MS_STR + k]);
                FMA16(acc[j], xv, wv0, wv1, wv2, wv3);
            }
        }
    }
    __syncthreads();
    #pragma unroll
    for (int j = 0; j < 4; j++) {
        float4 o;
        o.x = elu1(acc[j].x); o.y = elu1(acc[j].y);
        o.z = elu1(acc[j].z); o.w = elu1(acc[j].w);
        *reinterpret_cast<float4*>(&ms[(nq + j * 32) * MS_STR + oq * 4]) = o;
    }
    __syncthreads();

    // GEMM2 + LN + ELU + output
    {
        float4 bv = reinterpret_cast<const float4*>(b)[oq];
        #pragma unroll
        for (int j = 0; j < 4; j++) acc[j] = bv;
        #pragma unroll
        for (int k = 0; k < HF; k += 4) {
            float4 wv0 = *reinterpret_cast<const float4*>(&sw[(k+0) * HF + oq * 4]);
            float4 wv1 = *reinterpret_cast<const float4*>(&sw[(k+1) * HF + oq * 4]);
            float4 wv2 = *reinterpret_cast<const float4*>(&sw[(k+2) * HF + oq * 4]);
            float4 wv3 = *reinterpret_cast<const float4*>(&sw[(k+3) * HF + oq * 4]);
            #pragma unroll
            for (int j = 0; j < 4; j++) {
                float4 xv = *reinterpret_cast<const float4*>(&ms[(nq + j * 32) * MS_STR + k]);
                FMA16(acc[j], xv, wv0, wv1, wv2, wv3);
            }
        }
        float4 gv  = reinterpret_cast<const float4*>(g)[oq];
        float4 bev = reinterpret_cast<const float4*>(be)[oq];
        float4 wov = make_float4(0.f, 0.f, 0.f, 0.f); float bo = 0.f;
        if (MODE == 1) { wov = reinterpret_cast<const float4*>(wout)[oq]; bo = bout[0]; }
        #pragma unroll
        for (int j = 0; j < 4; j++) {
            int node = base + nq + j * 32;
            float4 a = acc[j];
            float mu = sum8(a.x + a.y + a.z + a.w) * (1.f / HF);
            float dx = a.x - mu, dy = a.y - mu, dz = a.z - mu, dw = a.w - mu;
            float var = sum8(dx*dx + dy*dy + dz*dz + dw*dw) * (1.f / HF);
            float r = rsqrtf(var + LN_EPS);
            float hx = elu1(dx * r * gv.x + bev.x);
            float hy = elu1(dy * r * gv.y + bev.y);
            float hz = elu1(dz * r * gv.z + bev.z);
            float hw = elu1(dw * r * gv.w + bev.w);
            if (MODE == 0) {
                float s = g_ns[node];   // pad: ns==0 -> zeros into pad rows (harmless)
                store_h4(&g_hs[(size_t)node * HF + oq * 4], hx * s, hy * s, hz * s, hw * s);
            } else {
                float partial = hx * wov.x + hy * wov.y + hz * wov.z + hw * wov.w;
                float dot = sum8(partial) + bo;
                if (oq == 0 && node < N_ATOMS) atomicAdd(&sacc[gid[node]], elu1(dot));
            }
        }
    }
    if (MODE == 1) {
        __syncthreads();
        for (int j = t; j < NGRAPH; j += 256) {
            float v = sacc[j];
            if (v != 0.f) atomicAdd(&out[j], v);
        }
    }
}

// -------- launch --------
extern "C" void kernel_launch(void* const* d_in, const int* in_sizes, int n_in,
                              void* d_out, int out_size) {
    const float* feats = (const float*)d_in[0];
    const int*   src   = (const int*)  d_in[1];
    const int*   dst   = (const int*)  d_in[2];
    const int*   gid   = (const int*)  d_in[3];
    const float* w0    = (const float*)d_in[4];
    const float* b0    = (const float*)d_in[5];
    const float* g0    = (const float*)d_in[6];
    const float* be0   = (const float*)d_in[7];
    const float* wc1   = (const float*)d_in[8];
    const float* bc1   = (const float*)d_in[9];
    const float* w1    = (const float*)d_in[10];
    const float* b1    = (const float*)d_in[11];
    const float* g1    = (const float*)d_in[12];
    const float* be1   = (const float*)d_in[13];
    const float* wc2   = (const float*)d_in[14];
    const float* bc2   = (const float*)d_in[15];
    const float* w2    = (const float*)d_in[16];
    const float* b2    = (const float*)d_in[17];
    const float* g2    = (const float*)d_in[18];
    const float* be2   = (const float*)d_in[19];
    const float* wout  = (const float*)d_in[20];
    const float* bout  = (const float*)d_in[21];
    float* out = (float*)d_out;

    const int TPB = 256;
    int tile_i_blocks = (N_ATOMS + TILE_I - 1) / TILE_I;   // 7813
    int tile_n_blocks = N_PAD / TILE_N;                    // 7813
    int node_blocks   = (N_ATOMS + TPB - 1) / TPB;
    int edge_blocks   = (N_EDGES + TPB - 1) / TPB;
    long long sc_threads = (long long)N_EDGES * 4;
    int sc_blocks = (int)((sc_threads + TPB - 1) / TPB);

    degree_kernel<<<edge_blocks, TPB>>>(src, dst);
    norm_kernel<<<node_blocks, TPB>>>(out);               // also zeroes out[]

    input_mlp_tile<<<tile_i_blocks, TPB>>>(feats, w0, b0, g0, be0);

    // conv 1: dst-blocked scatter (two L2-resident passes), then node block
    scatter_kernel<<<sc_blocks, TPB>>>(src, dst, 0, DSPLIT);
    scatter_kernel<<<sc_blocks, TPB>>>(src, dst, DSPLIT, N_ATOMS);
    node_block_tile<0><<<tile_n_blocks, TPB>>>(wc1, bc1, w1, b1, g1, be1, wout, bout, gid, out);

    // conv 2 + fused head
    scatter_kernel<<<sc_blocks, TPB>>>(src, dst, 0, DSPLIT);
    scatter_kernel<<<sc_blocks, TPB>>>(src, dst, DSPLIT, N_ATOMS);
    node_block_tile<1><<<tile_n_blocks, TPB>>>(wc2, bc2, w2, b2, g2, be2, wout, bout, gid, out);
}

// round 13
// speedup vs baseline: 1.2166x; 1.2166x over previous
#include <cuda_runtime.h>
#include <cuda_fp16.h>
#include <cuda_bf16.h>
#include <math.h>

#define N_ATOMS 1000000
#define N_PAD   1000064        // next multiple of 128
#define N_EDGES 4000000
#define NGRAPH  1024
#define IN_F    64
#define HF      32
#define LN_EPS  1e-5f
#define TILE_I  128
#define TILE_N  128
#define XS_STR  68
#define MS_STR  36

// -------- scratch (device globals: zero-initialized at module load) --------
__device__ float  g_deg_out[N_ATOMS];   // invariant: all-zero between launches
__device__ float  g_deg_in[N_ATOMS];    // invariant: all-zero between launches
__device__ float  g_ns[N_PAD];          // pad entries stay 0
__device__ float  g_nd[N_PAD];          // pad entries stay 0
__device__ __half g_hs[N_PAD * HF];     // fp16 messages (pad rows zeroed, never gathered)
__device__ __half g_m [N_PAD * HF];     // fp16 scatter accumulator (all-zero invariant)

// -------- helpers --------
__device__ __forceinline__ float elu1(float x) { return x > 0.f ? x : __expf(x) - 1.f; }
__device__ __forceinline__ float sum8(float v) {
    v += __shfl_xor_sync(0xffffffffu, v, 1);
    v += __shfl_xor_sync(0xffffffffu, v, 2);
    v += __shfl_xor_sync(0xffffffffu, v, 4);
    return v;
}

// -------- degree (4 edges/thread, vector index loads) --------
__global__ void degree_kernel(const int* __restrict__ src, const int* __restrict__ dst) {
    int i = blockIdx.x * blockDim.x + threadIdx.x;
    if (i < N_EDGES / 4) {
        int4 s4 = __ldg(&reinterpret_cast<const int4*>(src)[i]);
        int4 d4 = __ldg(&reinterpret_cast<const int4*>(dst)[i]);
        atomicAdd(&g_deg_out[s4.x], 1.f); atomicAdd(&g_deg_out[s4.y], 1.f);
        atomicAdd(&g_deg_out[s4.z], 1.f); atomicAdd(&g_deg_out[s4.w], 1.f);
        atomicAdd(&g_deg_in [d4.x], 1.f); atomicAdd(&g_deg_in [d4.y], 1.f);
        atomicAdd(&g_deg_in [d4.z], 1.f); atomicAdd(&g_deg_in [d4.w], 1.f);
    }
}
// reads degrees, writes norms, restores zero invariant, zeroes output buffer
__global__ void norm_kernel(float* __restrict__ out) {
    int i = blockIdx.x * blockDim.x + threadIdx.x;
    if (i < NGRAPH) out[i] = 0.f;
    if (i < N_ATOMS) {
        float dout = g_deg_out[i], din = g_deg_in[i];
        g_ns[i] = dout > 0.f ? rsqrtf(dout) : 0.f;
        g_nd[i] = din  > 0.f ? rsqrtf(din)  : 0.f;
        g_deg_out[i] = 0.f;
        g_deg_in [i] = 0.f;
    }
}

__device__ __forceinline__ void store_h4(__half* p, float a, float b, float c, float d) {
    __half2 lo = __floats2half2_rn(a, b);
    __half2 hi = __floats2half2_rn(c, d);
    uint2 v;
    v.x = *reinterpret_cast<unsigned*>(&lo);
    v.y = *reinterpret_cast<unsigned*>(&hi);
    *reinterpret_cast<uint2*>(p) = v;
}

#define FMA16(acc, xv, wv0, wv1, wv2, wv3)                                                     \
    do {                                                                                       \
        acc.x = fmaf(xv.x, wv0.x, acc.x); acc.y = fmaf(xv.x, wv0.y, acc.y);                    \
        acc.z = fmaf(xv.x, wv0.z, acc.z); acc.w = fmaf(xv.x, wv0.w, acc.w);                    \
        acc.x = fmaf(xv.y, wv1.x, acc.x); acc.y = fmaf(xv.y, wv1.y, acc.y);                    \
        acc.z = fmaf(xv.y, wv1.z, acc.z); acc.w = fmaf(xv.y, wv1.w, acc.w);                    \
        acc.x = fmaf(xv.z, wv2.x, acc.x); acc.y = fmaf(xv.z, wv2.y, acc.y);                    \
        acc.z = fmaf(xv.z, wv2.z, acc.z); acc.w = fmaf(xv.z, wv2.w, acc.w);                    \
        acc.x = fmaf(xv.w, wv3.x, acc.x); acc.y = fmaf(xv.w, wv3.y, acc.y);                    \
        acc.z = fmaf(xv.w, wv3.z, acc.z); acc.w = fmaf(xv.w, wv3.w, acc.w);                    \
    } while (0)

// -------- input MLP (tiled, 4 nodes/thread) --------
__global__ __launch_bounds__(256) void input_mlp_tile(
        const float* __restrict__ feats,
        const float* __restrict__ w0,  const float* __restrict__ b0,
        const float* __restrict__ g0,  const float* __restrict__ be0) {
    __shared__ float xs[TILE_I * XS_STR];
    __shared__ float sw[IN_F * HF];
    int t = threadIdx.x;
    int base = blockIdx.x * TILE_I;

    for (int i = t; i < IN_F * HF / 4; i += 256)
        reinterpret_cast<float4*>(sw)[i] = reinterpret_cast<const float4*>(w0)[i];
    #pragma unroll
    for (int i = t; i < TILE_I * (IN_F / 4); i += 256) {
        int n = i >> 4, c = i & 15;
        float4 v = make_float4(0.f, 0.f, 0.f, 0.f);
        if (base + n < N_ATOMS)
            v = reinterpret_cast<const float4*>(feats)[(size_t)(base + n) * 16 + c];
        *reinterpret_cast<float4*>(&xs[n * XS_STR + c * 4]) = v;
    }
    __syncthreads();

    int oq = t & 7, nq = t >> 3;
    float4 bv = reinterpret_cast<const float4*>(b0)[oq];
    float4 acc[4];
    #pragma unroll
    for (int j = 0; j < 4; j++) acc[j] = bv;

    #pragma unroll
    for (int k = 0; k < IN_F; k += 4) {
        float4 wv0 = *reinterpret_cast<const float4*>(&sw[(k+0) * HF + oq * 4]);
        float4 wv1 = *reinterpret_cast<const float4*>(&sw[(k+1) * HF + oq * 4]);
        float4 wv2 = *reinterpret_cast<const float4*>(&sw[(k+2) * HF + oq * 4]);
        float4 wv3 = *reinterpret_cast<const float4*>(&sw[(k+3) * HF + oq * 4]);
        #pragma unroll
        for (int j = 0; j < 4; j++) {
            float4 xv = *reinterpret_cast<const float4*>(&xs[(nq + j * 32) * XS_STR + k]);
            FMA16(acc[j], xv, wv0, wv1, wv2, wv3);
        }
    }

    float4 gv  = reinterpret_cast<const float4*>(g0)[oq];
    float4 bev = reinterpret_cast<const float4*>(be0)[oq];
    #pragma unroll
    for (int j = 0; j < 4; j++) {
        int node = base + nq + j * 32;
        float4 a = acc[j];
        float mu = sum8(a.x + a.y + a.z + a.w) * (1.f / HF);
        float dx = a.x - mu, dy = a.y - mu, dz = a.z - mu, dw = a.w - mu;
        float var = sum8(dx*dx + dy*dy + dz*dz + dw*dw) * (1.f / HF);
        float r = rsqrtf(var + LN_EPS);
        if (node < N_ATOMS) {
            float s = g_ns[node];
            store_h4(&g_hs[(size_t)node * HF + oq * 4],
                     elu1(dx * r * gv.x + bev.x) * s,
                     elu1(dy * r * gv.y + bev.y) * s,
                     elu1(dz * r * gv.z + bev.z) * s,
                     elu1(dw * r * gv.w + bev.w) * s);
        }
    }
}

// -------- edge scatter (single pass): m[dst] += hs[src] --------
__global__ void scatter_kernel(const int* __restrict__ src, const int* __restrict__ dst) {
    long long idx = (long long)blockIdx.x * blockDim.x + threadIdx.x;
    if (idx >= (long long)N_EDGES * 4) return;
    int e = (int)(idx >> 2);
    int p = ((int)idx & 3) * 8;
    int s = __ldg(&src[e]);
    int d = __ldg(&dst[e]);
    uint4 v = __ldg(reinterpret_cast<const uint4*>(&g_hs[(size_t)s * HF + p]));
    __half* mp = &g_m[(size_t)d * HF + p];
    asm volatile("red.global.add.noftz.v4.f16x2 [%0], {%1, %2, %3, %4};"
                 :: "l"(mp), "r"(v.x), "r"(v.y), "r"(v.z), "r"(v.w) : "memory");
}

// -------- conv epilogue + node MLP block (tiled, 4 nodes/thread, smem-lean) --------
// MODE 0: -> g_hs (half, *ns). MODE 1: fused head -> per-graph sums.
template<int MODE>
__global__ __launch_bounds__(256) void node_block_tile(
        const float* __restrict__ wc, const float* __restrict__ bc,
        const float* __restrict__ w,  const float* __restrict__ b,
        const float* __restrict__ g,  const float* __restrict__ be,
        const float* __restrict__ wout, const float* __restrict__ bout,
        const int* __restrict__ gid, float* __restrict__ out) {
    __shared__ float ms[TILE_N * MS_STR];              // reused for intermediate t
    __shared__ float swc[HF * HF];
    __shared__ float sw [HF * HF];
    __shared__ float sacc[MODE == 1 ? NGRAPH : 1];
    int t = threadIdx.x;
    int base = blockIdx.x * TILE_N;

    for (int i = t; i < HF * HF; i += 256) { swc[i] = wc[i]; sw[i] = w[i]; }
    if (MODE == 1)
        for (int i = t; i < NGRAPH; i += 256) sacc[i] = 0.f;
    #pragma unroll
    for (int i = t; i < TILE_N * 4; i += 256) {
        int n = i >> 2, c = i & 3;
        uint4* gp = reinterpret_cast<uint4*>(&g_m[(size_t)(base + n) * HF + c * 8]);
        uint4 v = *gp;
        float ndv = g_nd[base + n];
        float* mrow = &ms[n * MS_STR + c * 8];
        __half2 h;
        h = *reinterpret_cast<__half2*>(&v.x); float2 f0 = __half22float2(h);
        h = *reinterpret_cast<__half2*>(&v.y); float2 f1 = __half22float2(h);
        h = *reinterpret_cast<__half2*>(&v.z); float2 f2 = __half22float2(h);
        h = *reinterpret_cast<__half2*>(&v.w); float2 f3 = __half22float2(h);
        mrow[0] = f0.x * ndv; mrow[1] = f0.y * ndv;
        mrow[2] = f1.x * ndv; mrow[3] = f1.y * ndv;
        mrow[4] = f2.x * ndv; mrow[5] = f2.y * ndv;
        mrow[6] = f3.x * ndv; mrow[7] = f3.y * ndv;
        *gp = make_uint4(0u, 0u, 0u, 0u);
    }
    __syncthreads();

    int oq = t & 7, nq = t >> 3;

    // GEMM1 into registers: acc = ms @ wc + bc
    float4 acc[4];
    {
        float4 bv = reinterpret_cast<const float4*>(bc)[oq];
        #pragma unroll
        for (int j = 0; j < 4; j++) acc[j] = bv;
        #pragma unroll
        for (int k = 0; k < HF; k += 4) {
            float4 wv0 = *reinterpret_cast<const float4*>(&swc[(k+0) * HF + oq * 4]);
            float4 wv1 = *reinterpret_cast<const float4*>(&swc[(k+1) * HF + oq * 4]);
            float4 wv2 = *reinterpret_cast<const float4*>(&swc[(k+2) * HF + oq * 4]);
            float4 wv3 = *reinterpret_cast<const float4*>(&swc[(k+3) * HF + oq * 4]);
            #pragma unroll
            for (int j = 0; j < 4; j++) {
                float4 xv = *reinterpret_cast<const float4*>(&ms[(nq + j * 32) * MS_STR + k]);
                FMA16(acc[j], xv, wv0, wv1, wv2, wv3);
            }
        }
    }
    __syncthreads();
    #pragma unroll
    for (int j = 0; j < 4; j++) {
        float4 o;
        o.x = elu1(acc[j].x); o.y = elu1(acc[j].y);
        o.z = elu1(acc[j].z); o.w = elu1(acc[j].w);
        *reinterpret_cast<float4*>(&ms[(nq + j * 32) * MS_STR + oq * 4]) = o;
    }
    __syncthreads();

    // GEMM2 + LN + ELU + output
    {
        float4 bv = reinterpret_cast<const float4*>(b)[oq];
        #pragma unroll
        for (int j = 0; j < 4; j++) acc[j] = bv;
        #pragma unroll
        for (int k = 0; k < HF; k += 4) {
            float4 wv0 = *reinterpret_cast<const float4*>(&sw[(k+0) * HF + oq * 4]);
            float4 wv1 = *reinterpret_cast<const float4*>(&sw[(k+1) * HF + oq * 4]);
            float4 wv2 = *reinterpret_cast<const float4*>(&sw[(k+2) * HF + oq * 4]);
            float4 wv3 = *reinterpret_cast<const float4*>(&sw[(k+3) * HF + oq * 4]);
            #pragma unroll
            for (int j = 0; j < 4; j++) {
                float4 xv = *reinterpret_cast<const float4*>(&ms[(nq + j * 32) * MS_STR + k]);
                FMA16(acc[j], xv, wv0, wv1, wv2, wv3);
            }
        }
        float4 gv  = reinterpret_cast<const float4*>(g)[oq];
        float4 bev = reinterpret_cast<const float4*>(be)[oq];
        float4 wov = make_float4(0.f, 0.f, 0.f, 0.f); float bo = 0.f;
        if (MODE == 1) { wov = reinterpret_cast<const float4*>(wout)[oq]; bo = bout[0]; }
        float dotj[4];
        #pragma unroll
        for (int j = 0; j < 4; j++) {
            int node = base + nq + j * 32;
            float4 a = acc[j];
            float mu = sum8(a.x + a.y + a.z + a.w) * (1.f / HF);
            float dx = a.x - mu, dy = a.y - mu, dz = a.z - mu, dw = a.w - mu;
            float var = sum8(dx*dx + dy*dy + dz*dz + dw*dw) * (1.f / HF);
            float r = rsqrtf(var + LN_EPS);
            float hx = elu1(dx * r * gv.x + bev.x);
            float hy = elu1(dy * r * gv.y + bev.y);
            float hz = elu1(dz * r * gv.z + bev.z);
            float hw = elu1(dw * r * gv.w + bev.w);
            if (MODE == 0) {
                float s = g_ns[node];   // pad: ns==0 -> zeros into pad rows (harmless)
                store_h4(&g_hs[(size_t)node * HF + oq * 4], hx * s, hy * s, hz * s, hw * s);
            } else {
                float partial = hx * wov.x + hy * wov.y + hz * wov.z + hw * wov.w;
                dotj[j] = sum8(partial) + bo;
            }
        }
        if (MODE == 1 && oq == 0) {
            // coalesce per-thread graph contributions (gid sorted -> usually 1 atomic)
            float run = 0.f; int run_gid = -1;
            #pragma unroll
            for (int j = 0; j < 4; j++) {
                int node = base + nq + j * 32;
                if (node < N_ATOMS) {
                    int gg = __ldg(&gid[node]);
                    float v = elu1(dotj[j]);
                    if (gg == run_gid) {
                        run += v;
                    } else {
                        if (run_gid >= 0) atomicAdd(&sacc[run_gid], run);
                        run_gid = gg; run = v;
                    }
                }
            }
            if (run_gid >= 0) atomicAdd(&sacc[run_gid], run);
        }
    }
    if (MODE == 1) {
        __syncthreads();
        for (int j = t; j < NGRAPH; j += 256) {
            float v = sacc[j];
            if (v != 0.f) atomicAdd(&out[j], v);
        }
    }
}

// -------- launch --------
extern "C" void kernel_launch(void* const* d_in, const int* in_sizes, int n_in,
                              void* d_out, int out_size) {
    const float* feats = (const float*)d_in[0];
    const int*   src   = (const int*)  d_in[1];
    const int*   dst   = (const int*)  d_in[2];
    const int*   gid   = (const int*)  d_in[3];
    const float* w0    = (const float*)d_in[4];
    const float* b0    = (const float*)d_in[5];
    const float* g0    = (const float*)d_in[6];
    const float* be0   = (const float*)d_in[7];
    const float* wc1   = (const float*)d_in[8];
    const float* bc1   = (const float*)d_in[9];
    const float* w1    = (const float*)d_in[10];
    const float* b1    = (const float*)d_in[11];
    const float* g1    = (const float*)d_in[12];
    const float* be1   = (const float*)d_in[13];
    const float* wc2   = (const float*)d_in[14];
    const float* bc2   = (const float*)d_in[15];
    const float* w2    = (const float*)d_in[16];
    const float* b2    = (const float*)d_in[17];
    const float* g2    = (const float*)d_in[18];
    const float* be2   = (const float*)d_in[19];
    const float* wout  = (const float*)d_in[20];
    const float* bout  = (const float*)d_in[21];
    float* out = (float*)d_out;

    const int TPB = 256;
    int tile_i_blocks = (N_ATOMS + TILE_I - 1) / TILE_I;   // 7813
    int tile_n_blocks = N_PAD / TILE_N;                    // 7813
    int node_blocks   = (N_ATOMS + TPB - 1) / TPB;
    int edge4_blocks  = (N_EDGES / 4 + TPB - 1) / TPB;
    long long sc_threads = (long long)N_EDGES * 4;
    int sc_blocks = (int)((sc_threads + TPB - 1) / TPB);

    degree_kernel<<<edge4_blocks, TPB>>>(src, dst);
    norm_kernel<<<node_blocks, TPB>>>(out);               // also zeroes out[]

    input_mlp_tile<<<tile_i_blocks, TPB>>>(feats, w0, b0, g0, be0);

    scatter_kernel<<<sc_blocks, TPB>>>(src, dst);
    node_block_tile<0><<<tile_n_blocks, TPB>>>(wc1, bc1, w1, b1, g1, be1, wout, bout, gid, out);

    scatter_kernel<<<sc_blocks, TPB>>>(src, dst);
    node_block_tile<1><<<tile_n_blocks, TPB>>>(wc2, bc2, w2, b2, g2, be2, wout, bout, gid, out);
}